// round 1
// baseline (speedup 1.0000x reference)
#include <cuda_runtime.h>
#include <math.h>

#define NTYPES 10000
#define NG     2000
#define KK     64
#define DEGIN  8
#define DEGEXT 16
#define NB     1024

// ---------------- scratch (device globals; no allocation allowed) ----------------
__device__ float g_IW[NTYPES * 128];   // impact @ W.T
__device__ float g_IM[NTYPES * 128];   // impact @ M.T
__device__ float g_E [NG * 128];       // softmax(per_graph)
__device__ float g_X [NG * 128];       // softmax(relu(ext))

// ============================================================================
// Kernel A: IW = impact @ W.T, IM = impact @ M.T   (10000 x 128, K=128)
// 64-row tiles, 256 threads, W/M transposed into smem, float4 loads,
// per-thread 8 rows x 4 cols x 2 outputs register tile.
// ============================================================================
#define A_WSTR 132
#define A_ASTR 68
#define SMEM_A ((2 * 128 * A_WSTR + 128 * A_ASTR) * 4)

__global__ void __launch_bounds__(256) kA(const float* __restrict__ impact,
                                          const float* __restrict__ W,
                                          const float* __restrict__ M) {
    extern __shared__ float sm[];
    float* sWt = sm;                       // [128][A_WSTR]  Wt[i][j] = W[j][i]
    float* sMt = sm + 128 * A_WSTR;
    float* sAt = sm + 2 * 128 * A_WSTR;    // [128][A_ASTR]  At[i][r]

    const int tid = threadIdx.x;
    const int rowBase = blockIdx.x * 64;

    for (int idx = tid; idx < 128 * 128; idx += 256) {
        int j = idx >> 7, i = idx & 127;
        sWt[i * A_WSTR + j] = W[idx];
        sMt[i * A_WSTR + j] = M[idx];
    }
    for (int idx = tid; idx < 64 * 128; idx += 256) {
        int r = idx >> 7, i = idx & 127;
        int row = rowBase + r;
        sAt[i * A_ASTR + r] = (row < NTYPES) ? impact[row * 128 + i] : 0.f;
    }
    __syncthreads();

    const int tx = tid & 31;   // 4-col group
    const int ty = tid >> 5;   // 8-row group
    float accW[8][4] = {};
    float accM[8][4] = {};

#pragma unroll 4
    for (int i = 0; i < 128; ++i) {
        const float4 wv = *(const float4*)(sWt + i * A_WSTR + (tx << 2));
        const float4 mv = *(const float4*)(sMt + i * A_WSTR + (tx << 2));
        const float4 a0 = *(const float4*)(sAt + i * A_ASTR + (ty << 3));
        const float4 a1 = *(const float4*)(sAt + i * A_ASTR + (ty << 3) + 4);
        const float av[8] = {a0.x, a0.y, a0.z, a0.w, a1.x, a1.y, a1.z, a1.w};
        const float wr[4] = {wv.x, wv.y, wv.z, wv.w};
        const float mr[4] = {mv.x, mv.y, mv.z, mv.w};
#pragma unroll
        for (int rr = 0; rr < 8; ++rr) {
#pragma unroll
            for (int cc = 0; cc < 4; ++cc) {
                accW[rr][cc] = fmaf(av[rr], wr[cc], accW[rr][cc]);
                accM[rr][cc] = fmaf(av[rr], mr[cc], accM[rr][cc]);
            }
        }
    }

#pragma unroll
    for (int rr = 0; rr < 8; ++rr) {
        int row = rowBase + (ty << 3) + rr;
        if (row < NTYPES) {
            float4 ow = make_float4(accW[rr][0], accW[rr][1], accW[rr][2], accW[rr][3]);
            float4 om = make_float4(accM[rr][0], accM[rr][1], accM[rr][2], accM[rr][3]);
            *(float4*)(g_IW + row * 128 + (tx << 2)) = ow;
            *(float4*)(g_IM + row * 128 + (tx << 2)) = om;
        }
    }
}

// ============================================================================
// Kernel B: per_graph[g,j] = sum_k relu( IW[nt[g,k]][j] + sum_d IM[nbt[g,k,d]][j] )
//           then E[g] = softmax(per_graph[g])
// One block per graph. 256 threads = 2 k-groups x 128 columns.
// ============================================================================
__global__ void __launch_bounds__(256) kB(const int* __restrict__ node_type,
                                          const int* __restrict__ nbr_type) {
    __shared__ int   sNT[64];
    __shared__ int   sNB[512];
    __shared__ float sv[128];
    __shared__ float swm[8];
    __shared__ float sws[8];

    const int tid = threadIdx.x;
    const int g = blockIdx.x;

    for (int idx = tid; idx < 64; idx += 256)  sNT[idx] = node_type[g * 64 + idx];
    for (int idx = tid; idx < 512; idx += 256) sNB[idx] = nbr_type[g * 512 + idx];
    __syncthreads();

    const int kg = tid >> 7;
    const int j = tid & 127;

    float acc = 0.f;
    for (int k = kg; k < 64; k += 2) {
        float s = g_IW[sNT[k] * 128 + j];
        const int* nb = &sNB[k * 8];
#pragma unroll
        for (int d = 0; d < 8; ++d)
            s += g_IM[nb[d] * 128 + j];
        acc += fmaxf(s, 0.f);
    }

    if (kg == 0) sv[j] = acc;
    __syncthreads();
    if (kg == 1) sv[j] += acc;
    __syncthreads();

    const float v = sv[j];
    // block max (dup over kg is fine for max)
    float m = v;
#pragma unroll
    for (int off = 16; off; off >>= 1)
        m = fmaxf(m, __shfl_xor_sync(0xffffffffu, m, off));
    const int warp = tid >> 5, lane = tid & 31;
    if (lane == 0) swm[warp] = m;
    __syncthreads();
    m = swm[0];
#pragma unroll
    for (int w = 1; w < 8; ++w) m = fmaxf(m, swm[w]);

    const float e = expf(v - m);
    float s = e;
#pragma unroll
    for (int off = 16; off; off >>= 1)
        s += __shfl_xor_sync(0xffffffffu, s, off);
    if (lane == 0) sws[warp] = s;
    __syncthreads();
    // sum only warps 0..3 (kg==0 copy) to avoid double count
    float tot = sws[0] + sws[1] + sws[2] + sws[3];

    if (kg == 0) g_E[g * 128 + j] = e / tot;
}

// ============================================================================
// Kernel C: ext = E @ U.T + Esum @ V.T ;  X = softmax(relu(ext))
// 32-row tiles, 256 threads, fused Esum gather + dual GEMM + softmax epilogue.
// ============================================================================
#define C_WSTR 132
#define C_ASTR 36
#define SMEM_C ((2 * 128 * C_WSTR + 2 * 128 * C_ASTR) * 4 + 512 * 4)

__global__ void __launch_bounds__(256) kC(const float* __restrict__ U,
                                          const float* __restrict__ V,
                                          const int* __restrict__ ext_nbr) {
    extern __shared__ float sm[];
    float* sUt = sm;
    float* sVt = sUt + 128 * C_WSTR;
    float* sEt = sVt + 128 * C_WSTR;     // [128][C_ASTR] transposed E tile
    float* sSt = sEt + 128 * C_ASTR;     // [128][C_ASTR] transposed Esum tile
    int*   sXN = (int*)(sSt + 128 * C_ASTR);  // [32*16]

    const int tid = threadIdx.x;
    const int rowBase = blockIdx.x * 32;

    for (int idx = tid; idx < 128 * 128; idx += 256) {
        int j = idx >> 7, i = idx & 127;
        sUt[i * C_WSTR + j] = U[idx];
        sVt[i * C_WSTR + j] = V[idx];
    }
    for (int idx = tid; idx < 32 * 128; idx += 256) {
        int r = idx >> 7, i = idx & 127;
        int row = rowBase + r;
        sEt[i * C_ASTR + r] = (row < NG) ? g_E[row * 128 + i] : 0.f;
    }
    for (int idx = tid; idx < 512; idx += 256) {
        int row = rowBase + (idx >> 4);
        sXN[idx] = (row < NG) ? ext_nbr[row * 16 + (idx & 15)] : 0;
    }
    __syncthreads();

    // Esum tile (gather 16 E rows per graph)
    for (int idx = tid; idx < 32 * 128; idx += 256) {
        int r = idx >> 7, i = idx & 127;
        const int* xn = &sXN[r * 16];
        float s = 0.f;
#pragma unroll
        for (int d = 0; d < 16; ++d)
            s += g_E[xn[d] * 128 + i];
        sSt[i * C_ASTR + r] = s;
    }
    __syncthreads();

    const int tx = tid & 31;  // 4 cols
    const int ty = tid >> 5;  // 4 rows
    float acc[4][4] = {};

#pragma unroll 4
    for (int i = 0; i < 128; ++i) {
        const float4 uv = *(const float4*)(sUt + i * C_WSTR + (tx << 2));
        const float4 vv = *(const float4*)(sVt + i * C_WSTR + (tx << 2));
        const float4 ev = *(const float4*)(sEt + i * C_ASTR + (ty << 2));
        const float4 qv = *(const float4*)(sSt + i * C_ASTR + (ty << 2));
        const float er[4] = {ev.x, ev.y, ev.z, ev.w};
        const float sr[4] = {qv.x, qv.y, qv.z, qv.w};
        const float ur[4] = {uv.x, uv.y, uv.z, uv.w};
        const float vr[4] = {vv.x, vv.y, vv.z, vv.w};
#pragma unroll
        for (int rr = 0; rr < 4; ++rr) {
#pragma unroll
            for (int cc = 0; cc < 4; ++cc) {
                acc[rr][cc] = fmaf(er[rr], ur[cc], acc[rr][cc]);
                acc[rr][cc] = fmaf(sr[rr], vr[cc], acc[rr][cc]);
            }
        }
    }

    // relu + softmax per row (row's 128 cols live in one warp: ty fixed per warp)
#pragma unroll
    for (int rr = 0; rr < 4; ++rr) {
        int row = rowBase + (ty << 2) + rr;
        float v0 = fmaxf(acc[rr][0], 0.f);
        float v1 = fmaxf(acc[rr][1], 0.f);
        float v2 = fmaxf(acc[rr][2], 0.f);
        float v3 = fmaxf(acc[rr][3], 0.f);
        float m = fmaxf(fmaxf(v0, v1), fmaxf(v2, v3));
#pragma unroll
        for (int off = 16; off; off >>= 1)
            m = fmaxf(m, __shfl_xor_sync(0xffffffffu, m, off));
        float e0 = expf(v0 - m), e1 = expf(v1 - m), e2 = expf(v2 - m), e3 = expf(v3 - m);
        float s = e0 + e1 + e2 + e3;
#pragma unroll
        for (int off = 16; off; off >>= 1)
            s += __shfl_xor_sync(0xffffffffu, s, off);
        if (row < NG) {
            float inv = 1.f / s;
            float4 o = make_float4(e0 * inv, e1 * inv, e2 * inv, e3 * inv);
            *(float4*)(g_X + row * 128 + (tx << 2)) = o;
        }
    }
}

// ============================================================================
// Kernel D: e1=X[b0], e2=X[b1]; feat=[e1*e2, e1+e2];
//           h = relu(feat @ W1.T + b1); out = softmax(h @ W2.T + b2)
// 64 blocks x 16 rows; 256 threads = 2 row-groups x 128 cols; W1^T in smem.
// ============================================================================
#define D_WSTR 132
#define SMEM_D (256 * D_WSTR * 4)

__global__ void __launch_bounds__(256) kD(const int* __restrict__ batch,
                                          const float* __restrict__ W1,
                                          const float* __restrict__ b1,
                                          const float* __restrict__ W2,
                                          const float* __restrict__ b2,
                                          float* __restrict__ out) {
    extern __shared__ float sW1t[];     // [256][D_WSTR]: sW1t[i][j] = W1[j][i]
    __shared__ float sW2[256];
    __shared__ float sB1[128];
    __shared__ float sFp[2][128];
    __shared__ float sFs[2][128];
    __shared__ float sP0[8];
    __shared__ float sP1[8];

    const int tid = threadIdx.x;
    const int rg = tid >> 7;
    const int j = tid & 127;
    const int warp = tid >> 5, lane = tid & 31;

    for (int idx = tid; idx < 128 * 256; idx += 256) {
        int jw = idx >> 8, i = idx & 255;     // W1[jw][i], jw<128, i<256
        sW1t[i * D_WSTR + jw] = W1[idx];
    }
    sW2[tid] = W2[tid & 255];
    if (tid < 128) sB1[tid] = b1[tid];
    const float bb0 = b2[0], bb1 = b2[1];
    __syncthreads();

    for (int sweep = 0; sweep < 8; ++sweep) {
        const int row = blockIdx.x * 16 + sweep * 2 + rg;   // < 1024 always
        const int g1 = batch[2 * row];
        const int g2 = batch[2 * row + 1];
        const float e1 = g_X[g1 * 128 + j];
        const float e2 = g_X[g2 * 128 + j];
        sFp[rg][j] = e1 * e2;
        sFs[rg][j] = e1 + e2;
        __syncthreads();

        float hA = 0.f, hB = 0.f, hC = 0.f, hD = 0.f;
#pragma unroll 4
        for (int i = 0; i < 128; i += 2) {
            hA = fmaf(sFp[rg][i],     sW1t[i * D_WSTR + j],           hA);
            hB = fmaf(sFs[rg][i],     sW1t[(i + 128) * D_WSTR + j],   hB);
            hC = fmaf(sFp[rg][i + 1], sW1t[(i + 1) * D_WSTR + j],     hC);
            hD = fmaf(sFs[rg][i + 1], sW1t[(i + 129) * D_WSTR + j],   hD);
        }
        float h = fmaxf((hA + hB) + (hC + hD) + sB1[j], 0.f);

        float p0 = h * sW2[j];
        float p1 = h * sW2[128 + j];
#pragma unroll
        for (int off = 16; off; off >>= 1) {
            p0 += __shfl_xor_sync(0xffffffffu, p0, off);
            p1 += __shfl_xor_sync(0xffffffffu, p1, off);
        }
        if (lane == 0) { sP0[warp] = p0; sP1[warp] = p1; }
        __syncthreads();

        if (j == 0) {   // tid == rg*128
            float o0 = bb0, o1 = bb1;
#pragma unroll
            for (int w = 0; w < 4; ++w) {
                o0 += sP0[rg * 4 + w];
                o1 += sP1[rg * 4 + w];
            }
            float m = fmaxf(o0, o1);
            float z0 = expf(o0 - m), z1 = expf(o1 - m);
            float inv = 1.f / (z0 + z1);
            out[row * 2]     = z0 * inv;
            out[row * 2 + 1] = z1 * inv;
        }
        __syncthreads();   // protect sFp/sFs reuse
    }
}

// ============================================================================
extern "C" void kernel_launch(void* const* d_in, const int* in_sizes, int n_in,
                              void* d_out, int out_size) {
    const int*   batch     = (const int*)d_in[0];
    const int*   node_type = (const int*)d_in[1];
    const int*   nbr_type  = (const int*)d_in[2];
    const int*   ext_nbr   = (const int*)d_in[3];
    const float* impact    = (const float*)d_in[4];
    const float* W         = (const float*)d_in[5];
    const float* M         = (const float*)d_in[6];
    const float* U         = (const float*)d_in[7];
    const float* V         = (const float*)d_in[8];
    const float* W1        = (const float*)d_in[9];
    const float* b1        = (const float*)d_in[10];
    const float* W2        = (const float*)d_in[11];
    const float* b2        = (const float*)d_in[12];
    float* out = (float*)d_out;

    cudaFuncSetAttribute(kA, cudaFuncAttributeMaxDynamicSharedMemorySize, SMEM_A);
    cudaFuncSetAttribute(kC, cudaFuncAttributeMaxDynamicSharedMemorySize, SMEM_C);
    cudaFuncSetAttribute(kD, cudaFuncAttributeMaxDynamicSharedMemorySize, SMEM_D);

    kA<<<(NTYPES + 63) / 64, 256, SMEM_A>>>(impact, W, M);
    kB<<<NG, 256>>>(node_type, nbr_type);
    kC<<<(NG + 31) / 32, 256, SMEM_C>>>(U, V, ext_nbr);
    kD<<<NB / 16, 256, SMEM_D>>>(batch, W1, b1, W2, b2, out);
}

// round 2
// speedup vs baseline: 1.1502x; 1.1502x over previous
#include <cuda_runtime.h>
#include <math.h>

#define NTYPES 10000
#define NG     2000
#define NB     1024

// ---------------- scratch (device globals; no allocation allowed) ----------------
__device__ float g_IW[NTYPES * 128];   // impact @ W.T
__device__ float g_IM[NTYPES * 128];   // impact @ M.T
__device__ float g_E [NG * 128];       // softmax(per_graph)
__device__ float g_X [NG * 128];       // softmax(relu(ext))

// ============================================================================
// Kernel A: IW = impact @ W.T, IM = impact @ M.T   (10000 x 128, K=128)
// ============================================================================
#define A_WSTR 132
#define A_ASTR 68
#define SMEM_A ((2 * 128 * A_WSTR + 128 * A_ASTR) * 4)

__global__ void __launch_bounds__(256) kA(const float* __restrict__ impact,
                                          const float* __restrict__ W,
                                          const float* __restrict__ M) {
    extern __shared__ float sm[];
    float* sWt = sm;                       // [128][A_WSTR]  Wt[i][j] = W[j][i]
    float* sMt = sm + 128 * A_WSTR;
    float* sAt = sm + 2 * 128 * A_WSTR;    // [128][A_ASTR]  At[i][r]

    const int tid = threadIdx.x;
    const int rowBase = blockIdx.x * 64;

    for (int idx = tid; idx < 128 * 128; idx += 256) {
        int j = idx >> 7, i = idx & 127;
        sWt[i * A_WSTR + j] = W[idx];
        sMt[i * A_WSTR + j] = M[idx];
    }
    for (int idx = tid; idx < 64 * 128; idx += 256) {
        int r = idx >> 7, i = idx & 127;
        int row = rowBase + r;
        sAt[i * A_ASTR + r] = (row < NTYPES) ? impact[row * 128 + i] : 0.f;
    }
    __syncthreads();

    const int tx = tid & 31;   // 4-col group
    const int ty = tid >> 5;   // 8-row group
    float accW[8][4] = {};
    float accM[8][4] = {};

#pragma unroll 4
    for (int i = 0; i < 128; ++i) {
        const float4 wv = *(const float4*)(sWt + i * A_WSTR + (tx << 2));
        const float4 mv = *(const float4*)(sMt + i * A_WSTR + (tx << 2));
        const float4 a0 = *(const float4*)(sAt + i * A_ASTR + (ty << 3));
        const float4 a1 = *(const float4*)(sAt + i * A_ASTR + (ty << 3) + 4);
        const float av[8] = {a0.x, a0.y, a0.z, a0.w, a1.x, a1.y, a1.z, a1.w};
        const float wr[4] = {wv.x, wv.y, wv.z, wv.w};
        const float mr[4] = {mv.x, mv.y, mv.z, mv.w};
#pragma unroll
        for (int rr = 0; rr < 8; ++rr) {
#pragma unroll
            for (int cc = 0; cc < 4; ++cc) {
                accW[rr][cc] = fmaf(av[rr], wr[cc], accW[rr][cc]);
                accM[rr][cc] = fmaf(av[rr], mr[cc], accM[rr][cc]);
            }
        }
    }

#pragma unroll
    for (int rr = 0; rr < 8; ++rr) {
        int row = rowBase + (ty << 3) + rr;
        if (row < NTYPES) {
            float4 ow = make_float4(accW[rr][0], accW[rr][1], accW[rr][2], accW[rr][3]);
            float4 om = make_float4(accM[rr][0], accM[rr][1], accM[rr][2], accM[rr][3]);
            *(float4*)(g_IW + row * 128 + (tx << 2)) = ow;
            *(float4*)(g_IM + row * 128 + (tx << 2)) = om;
        }
    }
}

// ============================================================================
// Kernel B: per_graph[g,j] = sum_k relu( IW[nt[g,k]][j] + sum_d IM[nbt[g,k,d]][j] )
//           then E[g] = softmax(per_graph[g])
// One block per graph; 8 warps; warp w handles k = kk*8+w; float4 gathers.
// ============================================================================
__global__ void __launch_bounds__(256) kB(const int* __restrict__ node_type,
                                          const int* __restrict__ nbr_type) {
    __shared__ int   sNT[64];
    __shared__ int   sNB[512];
    __shared__ float sP[8][132];
    __shared__ float sredm[8];
    __shared__ float sreds[8];

    const int tid = threadIdx.x;
    const int g = blockIdx.x;
    const int w = tid >> 5, lane = tid & 31;

    if (tid < 64) sNT[tid] = node_type[g * 64 + tid];
    for (int idx = tid; idx < 512; idx += 256) sNB[idx] = nbr_type[g * 512 + idx];
    __syncthreads();

    float4 acc = make_float4(0.f, 0.f, 0.f, 0.f);
#pragma unroll 2
    for (int kk = 0; kk < 8; ++kk) {
        const int k = (kk << 3) + w;
        float4 s = *(const float4*)(g_IW + sNT[k] * 128 + (lane << 2));
        const int* nbp = &sNB[k << 3];
#pragma unroll
        for (int d = 0; d < 8; ++d) {
            const float4 v = *(const float4*)(g_IM + nbp[d] * 128 + (lane << 2));
            s.x += v.x; s.y += v.y; s.z += v.z; s.w += v.w;
        }
        acc.x += fmaxf(s.x, 0.f);
        acc.y += fmaxf(s.y, 0.f);
        acc.z += fmaxf(s.z, 0.f);
        acc.w += fmaxf(s.w, 0.f);
    }
    *(float4*)(&sP[w][lane << 2]) = acc;
    __syncthreads();

    float v = 0.f;
    if (tid < 128) {
#pragma unroll
        for (int ww = 0; ww < 8; ++ww) v += sP[ww][tid];
    }
    float m = v;
#pragma unroll
    for (int off = 16; off; off >>= 1)
        m = fmaxf(m, __shfl_xor_sync(0xffffffffu, m, off));
    if (lane == 0) sredm[w] = m;
    __syncthreads();
    const float M = fmaxf(fmaxf(sredm[0], sredm[1]), fmaxf(sredm[2], sredm[3]));

    const float e = (tid < 128) ? expf(v - M) : 0.f;
    float s = e;
#pragma unroll
    for (int off = 16; off; off >>= 1)
        s += __shfl_xor_sync(0xffffffffu, s, off);
    if (lane == 0) sreds[w] = s;
    __syncthreads();
    const float tot = sreds[0] + sreds[1] + sreds[2] + sreds[3];

    if (tid < 128) g_E[g * 128 + tid] = e / tot;
}

// ============================================================================
// Kernel C: ext = E @ U.T + Esum @ V.T ;  X = softmax(relu(ext))
// ============================================================================
#define C_WSTR 132
#define C_ASTR 36
#define SMEM_C ((2 * 128 * C_WSTR + 2 * 128 * C_ASTR) * 4 + 512 * 4)

__global__ void __launch_bounds__(256) kC(const float* __restrict__ U,
                                          const float* __restrict__ V,
                                          const int* __restrict__ ext_nbr) {
    extern __shared__ float sm[];
    float* sUt = sm;
    float* sVt = sUt + 128 * C_WSTR;
    float* sEt = sVt + 128 * C_WSTR;     // [128][C_ASTR] transposed E tile
    float* sSt = sEt + 128 * C_ASTR;     // [128][C_ASTR] transposed Esum tile
    int*   sXN = (int*)(sSt + 128 * C_ASTR);  // [32*16]

    const int tid = threadIdx.x;
    const int rowBase = blockIdx.x * 32;

    for (int idx = tid; idx < 128 * 128; idx += 256) {
        int j = idx >> 7, i = idx & 127;
        sUt[i * C_WSTR + j] = U[idx];
        sVt[i * C_WSTR + j] = V[idx];
    }
    for (int idx = tid; idx < 32 * 128; idx += 256) {
        int r = idx >> 7, i = idx & 127;
        int row = rowBase + r;
        sEt[i * C_ASTR + r] = (row < NG) ? g_E[row * 128 + i] : 0.f;
    }
    for (int idx = tid; idx < 512; idx += 256) {
        int row = rowBase + (idx >> 4);
        sXN[idx] = (row < NG) ? ext_nbr[row * 16 + (idx & 15)] : 0;
    }
    __syncthreads();

    for (int idx = tid; idx < 32 * 128; idx += 256) {
        int r = idx >> 7, i = idx & 127;
        const int* xn = &sXN[r * 16];
        float s = 0.f;
#pragma unroll
        for (int d = 0; d < 16; ++d)
            s += g_E[xn[d] * 128 + i];
        sSt[i * C_ASTR + r] = s;
    }
    __syncthreads();

    const int tx = tid & 31;  // 4 cols
    const int ty = tid >> 5;  // 4 rows
    float acc[4][4] = {};

#pragma unroll 4
    for (int i = 0; i < 128; ++i) {
        const float4 uv = *(const float4*)(sUt + i * C_WSTR + (tx << 2));
        const float4 vv = *(const float4*)(sVt + i * C_WSTR + (tx << 2));
        const float4 ev = *(const float4*)(sEt + i * C_ASTR + (ty << 2));
        const float4 qv = *(const float4*)(sSt + i * C_ASTR + (ty << 2));
        const float er[4] = {ev.x, ev.y, ev.z, ev.w};
        const float sr[4] = {qv.x, qv.y, qv.z, qv.w};
        const float ur[4] = {uv.x, uv.y, uv.z, uv.w};
        const float vr[4] = {vv.x, vv.y, vv.z, vv.w};
#pragma unroll
        for (int rr = 0; rr < 4; ++rr) {
#pragma unroll
            for (int cc = 0; cc < 4; ++cc) {
                acc[rr][cc] = fmaf(er[rr], ur[cc], acc[rr][cc]);
                acc[rr][cc] = fmaf(sr[rr], vr[cc], acc[rr][cc]);
            }
        }
    }

#pragma unroll
    for (int rr = 0; rr < 4; ++rr) {
        int row = rowBase + (ty << 2) + rr;
        float v0 = fmaxf(acc[rr][0], 0.f);
        float v1 = fmaxf(acc[rr][1], 0.f);
        float v2 = fmaxf(acc[rr][2], 0.f);
        float v3 = fmaxf(acc[rr][3], 0.f);
        float m = fmaxf(fmaxf(v0, v1), fmaxf(v2, v3));
#pragma unroll
        for (int off = 16; off; off >>= 1)
            m = fmaxf(m, __shfl_xor_sync(0xffffffffu, m, off));
        float e0 = expf(v0 - m), e1 = expf(v1 - m), e2 = expf(v2 - m), e3 = expf(v3 - m);
        float s = e0 + e1 + e2 + e3;
#pragma unroll
        for (int off = 16; off; off >>= 1)
            s += __shfl_xor_sync(0xffffffffu, s, off);
        if (row < NG) {
            float inv = 1.f / s;
            float4 o = make_float4(e0 * inv, e1 * inv, e2 * inv, e3 * inv);
            *(float4*)(g_X + row * 128 + (tx << 2)) = o;
        }
    }
}

// ============================================================================
// Kernel D: e1=X[b0], e2=X[b1]; feat=[e1*e2, e1+e2];
//           h = relu(feat @ W1.T + b1); out = softmax(h @ W2.T + b2)
// 128 blocks x 8 rows; 256 threads = 2 row-groups x 128 cols.
// W1 UNtransposed in smem, row stride 260 -> conflict-free LDS.128.
// ============================================================================
#define D_STR 260
#define SMEM_D (128 * D_STR * 4)

__global__ void __launch_bounds__(256) kD(const int* __restrict__ batch,
                                          const float* __restrict__ W1,
                                          const float* __restrict__ b1,
                                          const float* __restrict__ W2,
                                          const float* __restrict__ b2,
                                          float* __restrict__ out) {
    extern __shared__ float sW[];        // [128][D_STR]
    __shared__ float sF[2][260];         // feat per row-group (260 keeps 16B align)
    __shared__ float sW2[256];
    __shared__ float sB1[128];
    __shared__ float sP0[8];
    __shared__ float sP1[8];

    const int tid = threadIdx.x;
    const int rg = tid >> 7;
    const int j = tid & 127;
    const int warp = tid >> 5, lane = tid & 31;

    for (int idx = tid; idx < 128 * 256; idx += 256) {
        int jr = idx >> 8, i = idx & 255;
        sW[jr * D_STR + i] = W1[idx];
    }
    sW2[tid] = W2[tid];
    if (tid < 128) sB1[tid] = b1[tid];
    const float bb0 = b2[0], bb1 = b2[1];
    __syncthreads();

    for (int sweep = 0; sweep < 4; ++sweep) {
        const int row = blockIdx.x * 8 + sweep * 2 + rg;   // < 1024
        const int g1 = batch[2 * row];
        const int g2 = batch[2 * row + 1];
        const float e1 = g_X[g1 * 128 + j];
        const float e2 = g_X[g2 * 128 + j];
        sF[rg][j] = e1 * e2;
        sF[rg][128 + j] = e1 + e2;
        __syncthreads();

        float h0 = 0.f, h1 = 0.f, h2 = 0.f, h3 = 0.f;
#pragma unroll 8
        for (int m = 0; m < 64; ++m) {
            const float4 wv = *(const float4*)(sW + j * D_STR + (m << 2));
            const float4 fv = *(const float4*)(&sF[rg][m << 2]);
            h0 = fmaf(fv.x, wv.x, h0);
            h1 = fmaf(fv.y, wv.y, h1);
            h2 = fmaf(fv.z, wv.z, h2);
            h3 = fmaf(fv.w, wv.w, h3);
        }
        const float h = fmaxf(((h0 + h1) + (h2 + h3)) + sB1[j], 0.f);

        float p0 = h * sW2[j];
        float p1 = h * sW2[128 + j];
#pragma unroll
        for (int off = 16; off; off >>= 1) {
            p0 += __shfl_xor_sync(0xffffffffu, p0, off);
            p1 += __shfl_xor_sync(0xffffffffu, p1, off);
        }
        if (lane == 0) { sP0[warp] = p0; sP1[warp] = p1; }
        __syncthreads();

        if (j == 0) {   // one thread per row-group
            float o0 = bb0, o1 = bb1;
#pragma unroll
            for (int w2 = 0; w2 < 4; ++w2) {
                o0 += sP0[rg * 4 + w2];
                o1 += sP1[rg * 4 + w2];
            }
            const float mm = fmaxf(o0, o1);
            const float z0 = expf(o0 - mm), z1 = expf(o1 - mm);
            const float inv = 1.f / (z0 + z1);
            out[row * 2]     = z0 * inv;
            out[row * 2 + 1] = z1 * inv;
        }
        __syncthreads();   // protect sF / sP reuse
    }
}

// ============================================================================
extern "C" void kernel_launch(void* const* d_in, const int* in_sizes, int n_in,
                              void* d_out, int out_size) {
    const int*   batch     = (const int*)d_in[0];
    const int*   node_type = (const int*)d_in[1];
    const int*   nbr_type  = (const int*)d_in[2];
    const int*   ext_nbr   = (const int*)d_in[3];
    const float* impact    = (const float*)d_in[4];
    const float* W         = (const float*)d_in[5];
    const float* M         = (const float*)d_in[6];
    const float* U         = (const float*)d_in[7];
    const float* V         = (const float*)d_in[8];
    const float* W1        = (const float*)d_in[9];
    const float* b1        = (const float*)d_in[10];
    const float* W2        = (const float*)d_in[11];
    const float* b2        = (const float*)d_in[12];
    float* out = (float*)d_out;

    cudaFuncSetAttribute(kA, cudaFuncAttributeMaxDynamicSharedMemorySize, SMEM_A);
    cudaFuncSetAttribute(kC, cudaFuncAttributeMaxDynamicSharedMemorySize, SMEM_C);
    cudaFuncSetAttribute(kD, cudaFuncAttributeMaxDynamicSharedMemorySize, SMEM_D);

    kA<<<(NTYPES + 63) / 64, 256, SMEM_A>>>(impact, W, M);
    kB<<<NG, 256>>>(node_type, nbr_type);
    kC<<<(NG + 31) / 32, 256, SMEM_C>>>(U, V, ext_nbr);
    kD<<<NB / 8, 256, SMEM_D>>>(batch, W1, b1, W2, b2, out);
}

// round 3
// speedup vs baseline: 1.4167x; 1.2317x over previous
#include <cuda_runtime.h>
#include <cuda_fp16.h>
#include <math.h>

#define NTYPES 10000
#define NG     2000
#define NB     1024

// ---------------- scratch (device globals; no allocation allowed) ----------------
__device__ __half g_IWh[NTYPES * 128];   // impact @ W.T   (fp16)
__device__ __half g_IMh[NTYPES * 128];   // impact @ M.T   (fp16)
__device__ float  g_E [NG * 128];        // softmax(per_graph)
__device__ float  g_X [NG * 128];        // softmax(relu(ext))

__device__ __forceinline__ float4 ldh4(const __half* p) {
    const uint2 r = *(const uint2*)p;
    const float2 lo = __half22float2(*(const __half2*)&r.x);
    const float2 hi = __half22float2(*(const __half2*)&r.y);
    return make_float4(lo.x, lo.y, hi.x, hi.y);
}

// ============================================================================
// Kernel A: IW = impact @ W.T, IM = impact @ M.T  -> fp16 tables
// ============================================================================
#define A_WSTR 132
#define A_ASTR 68
#define SMEM_A ((2 * 128 * A_WSTR + 128 * A_ASTR) * 4)

__global__ void __launch_bounds__(256) kA(const float* __restrict__ impact,
                                          const float* __restrict__ W,
                                          const float* __restrict__ M) {
    extern __shared__ float sm[];
    float* sWt = sm;                       // [128][A_WSTR]  Wt[i][j] = W[j][i]
    float* sMt = sm + 128 * A_WSTR;
    float* sAt = sm + 2 * 128 * A_WSTR;    // [128][A_ASTR]  At[i][r]

    const int tid = threadIdx.x;
    const int rowBase = blockIdx.x * 64;

    for (int idx = tid; idx < 128 * 128; idx += 256) {
        int j = idx >> 7, i = idx & 127;
        sWt[i * A_WSTR + j] = W[idx];
        sMt[i * A_WSTR + j] = M[idx];
    }
    for (int idx = tid; idx < 64 * 128; idx += 256) {
        int r = idx >> 7, i = idx & 127;
        int row = rowBase + r;
        sAt[i * A_ASTR + r] = (row < NTYPES) ? impact[row * 128 + i] : 0.f;
    }
    __syncthreads();

    const int tx = tid & 31;   // 4-col group
    const int ty = tid >> 5;   // 8-row group
    float accW[8][4] = {};
    float accM[8][4] = {};

#pragma unroll 4
    for (int i = 0; i < 128; ++i) {
        const float4 wv = *(const float4*)(sWt + i * A_WSTR + (tx << 2));
        const float4 mv = *(const float4*)(sMt + i * A_WSTR + (tx << 2));
        const float4 a0 = *(const float4*)(sAt + i * A_ASTR + (ty << 3));
        const float4 a1 = *(const float4*)(sAt + i * A_ASTR + (ty << 3) + 4);
        const float av[8] = {a0.x, a0.y, a0.z, a0.w, a1.x, a1.y, a1.z, a1.w};
        const float wr[4] = {wv.x, wv.y, wv.z, wv.w};
        const float mr[4] = {mv.x, mv.y, mv.z, mv.w};
#pragma unroll
        for (int rr = 0; rr < 8; ++rr) {
#pragma unroll
            for (int cc = 0; cc < 4; ++cc) {
                accW[rr][cc] = fmaf(av[rr], wr[cc], accW[rr][cc]);
                accM[rr][cc] = fmaf(av[rr], mr[cc], accM[rr][cc]);
            }
        }
    }

#pragma unroll
    for (int rr = 0; rr < 8; ++rr) {
        int row = rowBase + (ty << 3) + rr;
        if (row < NTYPES) {
            __half2 w01 = __floats2half2_rn(accW[rr][0], accW[rr][1]);
            __half2 w23 = __floats2half2_rn(accW[rr][2], accW[rr][3]);
            __half2 m01 = __floats2half2_rn(accM[rr][0], accM[rr][1]);
            __half2 m23 = __floats2half2_rn(accM[rr][2], accM[rr][3]);
            uint2 pw, pm;
            pw.x = *(unsigned*)&w01; pw.y = *(unsigned*)&w23;
            pm.x = *(unsigned*)&m01; pm.y = *(unsigned*)&m23;
            *(uint2*)(g_IWh + row * 128 + (tx << 2)) = pw;
            *(uint2*)(g_IMh + row * 128 + (tx << 2)) = pm;
        }
    }
}

// ============================================================================
// Kernel B: per_graph[g,j] = sum_k relu( IW[nt[g,k]][j] + sum_d IM[nbt[g,k,d]][j] )
//           then E[g] = softmax(per_graph[g]).  fp16 gathers, fp32 accumulate.
// ============================================================================
__global__ void __launch_bounds__(256) kB(const int* __restrict__ node_type,
                                          const int* __restrict__ nbr_type) {
    __shared__ int   sNT[64];
    __shared__ int   sNB[512];
    __shared__ float sP[8][132];
    __shared__ float sredm[8];
    __shared__ float sreds[8];

    const int tid = threadIdx.x;
    const int g = blockIdx.x;
    const int w = tid >> 5, lane = tid & 31;

    if (tid < 64) sNT[tid] = node_type[g * 64 + tid];
    for (int idx = tid; idx < 512; idx += 256) sNB[idx] = nbr_type[g * 512 + idx];
    __syncthreads();

    const int co = lane << 2;
    float4 acc = make_float4(0.f, 0.f, 0.f, 0.f);
#pragma unroll 2
    for (int kk = 0; kk < 8; ++kk) {
        const int k = (kk << 3) + w;
        float4 s = ldh4(g_IWh + (size_t)sNT[k] * 128 + co);
        const int* nbp = &sNB[k << 3];
#pragma unroll
        for (int d = 0; d < 8; ++d) {
            const float4 v = ldh4(g_IMh + (size_t)nbp[d] * 128 + co);
            s.x += v.x; s.y += v.y; s.z += v.z; s.w += v.w;
        }
        acc.x += fmaxf(s.x, 0.f);
        acc.y += fmaxf(s.y, 0.f);
        acc.z += fmaxf(s.z, 0.f);
        acc.w += fmaxf(s.w, 0.f);
    }
    *(float4*)(&sP[w][co]) = acc;
    __syncthreads();

    float v = 0.f;
    if (tid < 128) {
#pragma unroll
        for (int ww = 0; ww < 8; ++ww) v += sP[ww][tid];
    }
    float m = v;
#pragma unroll
    for (int off = 16; off; off >>= 1)
        m = fmaxf(m, __shfl_xor_sync(0xffffffffu, m, off));
    if (lane == 0) sredm[w] = m;
    __syncthreads();
    const float M = fmaxf(fmaxf(sredm[0], sredm[1]), fmaxf(sredm[2], sredm[3]));

    const float e = (tid < 128) ? expf(v - M) : 0.f;
    float s = e;
#pragma unroll
    for (int off = 16; off; off >>= 1)
        s += __shfl_xor_sync(0xffffffffu, s, off);
    if (lane == 0) sreds[w] = s;
    __syncthreads();
    const float tot = sreds[0] + sreds[1] + sreds[2] + sreds[3];

    if (tid < 128) g_E[g * 128 + tid] = e / tot;
}

// ============================================================================
// Kernel C: ext = E @ U.T + Esum @ V.T ;  X = softmax(relu(ext))
// ============================================================================
#define C_WSTR 132
#define C_ASTR 36
#define SMEM_C ((2 * 128 * C_WSTR + 2 * 128 * C_ASTR) * 4 + 512 * 4)

__global__ void __launch_bounds__(256) kC(const float* __restrict__ U,
                                          const float* __restrict__ V,
                                          const int* __restrict__ ext_nbr) {
    extern __shared__ float sm[];
    float* sUt = sm;
    float* sVt = sUt + 128 * C_WSTR;
    float* sEt = sVt + 128 * C_WSTR;     // [128][C_ASTR] transposed E tile
    float* sSt = sEt + 128 * C_ASTR;     // [128][C_ASTR] transposed Esum tile
    int*   sXN = (int*)(sSt + 128 * C_ASTR);  // [32*16]

    const int tid = threadIdx.x;
    const int rowBase = blockIdx.x * 32;

    for (int idx = tid; idx < 128 * 128; idx += 256) {
        int j = idx >> 7, i = idx & 127;
        sUt[i * C_WSTR + j] = U[idx];
        sVt[i * C_WSTR + j] = V[idx];
    }
    for (int idx = tid; idx < 32 * 128; idx += 256) {
        int r = idx >> 7, i = idx & 127;
        int row = rowBase + r;
        sEt[i * C_ASTR + r] = (row < NG) ? g_E[row * 128 + i] : 0.f;
    }
    for (int idx = tid; idx < 512; idx += 256) {
        int row = rowBase + (idx >> 4);
        sXN[idx] = (row < NG) ? ext_nbr[row * 16 + (idx & 15)] : 0;
    }
    __syncthreads();

    // Esum tile: vectorized float4 gather of 16 E rows per graph
    for (int idx = tid; idx < 32 * 32; idx += 256) {
        int r = idx >> 5, c4 = (idx & 31) << 2;
        const int* xn = &sXN[r * 16];
        float4 s = make_float4(0.f, 0.f, 0.f, 0.f);
#pragma unroll
        for (int d = 0; d < 16; ++d) {
            const float4 v = *(const float4*)(g_E + xn[d] * 128 + c4);
            s.x += v.x; s.y += v.y; s.z += v.z; s.w += v.w;
        }
        sSt[(c4 + 0) * C_ASTR + r] = s.x;
        sSt[(c4 + 1) * C_ASTR + r] = s.y;
        sSt[(c4 + 2) * C_ASTR + r] = s.z;
        sSt[(c4 + 3) * C_ASTR + r] = s.w;
    }
    __syncthreads();

    const int tx = tid & 31;  // 4 cols
    const int ty = tid >> 5;  // 4 rows
    float acc[4][4] = {};

#pragma unroll 4
    for (int i = 0; i < 128; ++i) {
        const float4 uv = *(const float4*)(sUt + i * C_WSTR + (tx << 2));
        const float4 vv = *(const float4*)(sVt + i * C_WSTR + (tx << 2));
        const float4 ev = *(const float4*)(sEt + i * C_ASTR + (ty << 2));
        const float4 qv = *(const float4*)(sSt + i * C_ASTR + (ty << 2));
        const float er[4] = {ev.x, ev.y, ev.z, ev.w};
        const float sr[4] = {qv.x, qv.y, qv.z, qv.w};
        const float ur[4] = {uv.x, uv.y, uv.z, uv.w};
        const float vr[4] = {vv.x, vv.y, vv.z, vv.w};
#pragma unroll
        for (int rr = 0; rr < 4; ++rr) {
#pragma unroll
            for (int cc = 0; cc < 4; ++cc) {
                acc[rr][cc] = fmaf(er[rr], ur[cc], acc[rr][cc]);
                acc[rr][cc] = fmaf(sr[rr], vr[cc], acc[rr][cc]);
            }
        }
    }

#pragma unroll
    for (int rr = 0; rr < 4; ++rr) {
        int row = rowBase + (ty << 2) + rr;
        float v0 = fmaxf(acc[rr][0], 0.f);
        float v1 = fmaxf(acc[rr][1], 0.f);
        float v2 = fmaxf(acc[rr][2], 0.f);
        float v3 = fmaxf(acc[rr][3], 0.f);
        float m = fmaxf(fmaxf(v0, v1), fmaxf(v2, v3));
#pragma unroll
        for (int off = 16; off; off >>= 1)
            m = fmaxf(m, __shfl_xor_sync(0xffffffffu, m, off));
        float e0 = expf(v0 - m), e1 = expf(v1 - m), e2 = expf(v2 - m), e3 = expf(v3 - m);
        float s = e0 + e1 + e2 + e3;
#pragma unroll
        for (int off = 16; off; off >>= 1)
            s += __shfl_xor_sync(0xffffffffu, s, off);
        if (row < NG) {
            float inv = 1.f / s;
            float4 o = make_float4(e0 * inv, e1 * inv, e2 * inv, e3 * inv);
            *(float4*)(g_X + row * 128 + (tx << 2)) = o;
        }
    }
}

// ============================================================================
// Kernel D (single pass): 128 blocks x 8 rows; 256 threads.
// Thread (rg = tid>>7, j = tid&127) accumulates h[j] for 4 rows at once.
// ============================================================================
#define D_STR 260
#define SMEM_D (128 * D_STR * 4)

__global__ void __launch_bounds__(256) kD(const int* __restrict__ batch,
                                          const float* __restrict__ W1,
                                          const float* __restrict__ b1,
                                          const float* __restrict__ W2,
                                          const float* __restrict__ b2,
                                          float* __restrict__ out) {
    extern __shared__ float sW[];        // [128][D_STR]
    __shared__ float sF[8][260];         // feat per row (16B-aligned stride)
    __shared__ float sW2[256];
    __shared__ float sB1[128];
    __shared__ float sP[8][4][2];        // [warp][row-in-group][logit]

    const int tid = threadIdx.x;
    const int rg = tid >> 7;             // 0/1 -> rows rg*4 .. rg*4+3
    const int j = tid & 127;
    const int warp = tid >> 5, lane = tid & 31;

    // vectorized W1 fill: 32 float4 per thread, conflict-free STS.128
    for (int q = tid; q < 128 * 64; q += 256) {
        const float4 v = *(const float4*)(W1 + (q << 2));
        const int jr = q >> 6, i4 = (q & 63) << 2;
        *(float4*)(sW + jr * D_STR + i4) = v;
    }
    sW2[tid] = W2[tid];
    if (tid < 128) sB1[tid] = b1[tid];
    const float bb0 = b2[0], bb1 = b2[1];

    // feat fill: half = tid>>7 covers alternate rows
    for (int rr = rg; rr < 8; rr += 2) {
        const int row = blockIdx.x * 8 + rr;
        const int b0i = batch[2 * row];
        const int b1i = batch[2 * row + 1];
        const float e1 = g_X[b0i * 128 + j];
        const float e2 = g_X[b1i * 128 + j];
        sF[rr][j] = e1 * e2;
        sF[rr][128 + j] = e1 + e2;
    }
    __syncthreads();

    float4 a0 = make_float4(0.f, 0.f, 0.f, 0.f);
    float4 a1 = a0, a2 = a0, a3 = a0;
    const float* wrow = sW + j * D_STR;
    const int rb = rg << 2;
#pragma unroll 4
    for (int m = 0; m < 64; ++m) {
        const float4 wv = *(const float4*)(wrow + (m << 2));
        const float4 f0 = *(const float4*)(&sF[rb + 0][m << 2]);
        const float4 f1 = *(const float4*)(&sF[rb + 1][m << 2]);
        const float4 f2 = *(const float4*)(&sF[rb + 2][m << 2]);
        const float4 f3 = *(const float4*)(&sF[rb + 3][m << 2]);
        a0.x = fmaf(f0.x, wv.x, a0.x); a0.y = fmaf(f0.y, wv.y, a0.y);
        a0.z = fmaf(f0.z, wv.z, a0.z); a0.w = fmaf(f0.w, wv.w, a0.w);
        a1.x = fmaf(f1.x, wv.x, a1.x); a1.y = fmaf(f1.y, wv.y, a1.y);
        a1.z = fmaf(f1.z, wv.z, a1.z); a1.w = fmaf(f1.w, wv.w, a1.w);
        a2.x = fmaf(f2.x, wv.x, a2.x); a2.y = fmaf(f2.y, wv.y, a2.y);
        a2.z = fmaf(f2.z, wv.z, a2.z); a2.w = fmaf(f2.w, wv.w, a2.w);
        a3.x = fmaf(f3.x, wv.x, a3.x); a3.y = fmaf(f3.y, wv.y, a3.y);
        a3.z = fmaf(f3.z, wv.z, a3.z); a3.w = fmaf(f3.w, wv.w, a3.w);
    }

    const float bj = sB1[j];
    const float w2a = sW2[j], w2b = sW2[128 + j];
    float h0 = fmaxf((a0.x + a0.y) + (a0.z + a0.w) + bj, 0.f);
    float h1 = fmaxf((a1.x + a1.y) + (a1.z + a1.w) + bj, 0.f);
    float h2 = fmaxf((a2.x + a2.y) + (a2.z + a2.w) + bj, 0.f);
    float h3 = fmaxf((a3.x + a3.y) + (a3.z + a3.w) + bj, 0.f);

    float p00 = h0 * w2a, p01 = h0 * w2b;
    float p10 = h1 * w2a, p11 = h1 * w2b;
    float p20 = h2 * w2a, p21 = h2 * w2b;
    float p30 = h3 * w2a, p31 = h3 * w2b;
#pragma unroll
    for (int off = 16; off; off >>= 1) {
        p00 += __shfl_xor_sync(0xffffffffu, p00, off);
        p01 += __shfl_xor_sync(0xffffffffu, p01, off);
        p10 += __shfl_xor_sync(0xffffffffu, p10, off);
        p11 += __shfl_xor_sync(0xffffffffu, p11, off);
        p20 += __shfl_xor_sync(0xffffffffu, p20, off);
        p21 += __shfl_xor_sync(0xffffffffu, p21, off);
        p30 += __shfl_xor_sync(0xffffffffu, p30, off);
        p31 += __shfl_xor_sync(0xffffffffu, p31, off);
    }
    if (lane == 0) {
        sP[warp][0][0] = p00; sP[warp][0][1] = p01;
        sP[warp][1][0] = p10; sP[warp][1][1] = p11;
        sP[warp][2][0] = p20; sP[warp][2][1] = p21;
        sP[warp][3][0] = p30; sP[warp][3][1] = p31;
    }
    __syncthreads();

    if (tid < 8) {
        const int trg = tid >> 2, r = tid & 3;
        const int row = blockIdx.x * 8 + trg * 4 + r;
        float o0 = bb0, o1 = bb1;
#pragma unroll
        for (int w2 = 0; w2 < 4; ++w2) {
            o0 += sP[trg * 4 + w2][r][0];
            o1 += sP[trg * 4 + w2][r][1];
        }
        const float mm = fmaxf(o0, o1);
        const float z0 = expf(o0 - mm), z1 = expf(o1 - mm);
        const float inv = 1.f / (z0 + z1);
        out[row * 2]     = z0 * inv;
        out[row * 2 + 1] = z1 * inv;
    }
}

// ============================================================================
extern "C" void kernel_launch(void* const* d_in, const int* in_sizes, int n_in,
                              void* d_out, int out_size) {
    const int*   batch     = (const int*)d_in[0];
    const int*   node_type = (const int*)d_in[1];
    const int*   nbr_type  = (const int*)d_in[2];
    const int*   ext_nbr   = (const int*)d_in[3];
    const float* impact    = (const float*)d_in[4];
    const float* W         = (const float*)d_in[5];
    const float* M         = (const float*)d_in[6];
    const float* U         = (const float*)d_in[7];
    const float* V         = (const float*)d_in[8];
    const float* W1        = (const float*)d_in[9];
    const float* b1        = (const float*)d_in[10];
    const float* W2        = (const float*)d_in[11];
    const float* b2        = (const float*)d_in[12];
    float* out = (float*)d_out;

    cudaFuncSetAttribute(kA, cudaFuncAttributeMaxDynamicSharedMemorySize, SMEM_A);
    cudaFuncSetAttribute(kC, cudaFuncAttributeMaxDynamicSharedMemorySize, SMEM_C);
    cudaFuncSetAttribute(kD, cudaFuncAttributeMaxDynamicSharedMemorySize, SMEM_D);

    kA<<<(NTYPES + 63) / 64, 256, SMEM_A>>>(impact, W, M);
    kB<<<NG, 256>>>(node_type, nbr_type);
    kC<<<(NG + 31) / 32, 256, SMEM_C>>>(U, V, ext_nbr);
    kD<<<NB / 8, 256, SMEM_D>>>(batch, W1, b1, W2, b2, out);
}